// round 13
// baseline (speedup 1.0000x reference)
#include <cuda_runtime.h>
#include <cuda_bf16.h>

// ---------------------------------------------------------------------------
// SafetyLayer: per-car separable QP projection — single fused kernel.
//   Each thread owns ONE float4 column-vector (4 adjacent columns of D=512),
//   computes its per-column QP bounds inline, then streams down rows with an
//   8x-unrolled load/clip/decompose/store loop (streaming .cs stores).
//   8 independent LDG.128 in flight per thread; grid = 148 SMs x 4 blocks
//   = 592 = one exact wave at the expected ~64-reg budget.
// ---------------------------------------------------------------------------

#define D_COLS      512
#define NVEC_COLS   (D_COLS / 4)     // 128 float4 columns per row

// config constants
#define C_FINAL_SOC 0.97f
#define C_AC_MAX    0.165f           // 6.6/40
#define C_AD_MAG    0.165f
#define C_ETA_C     0.95f
#define C_ETA_D     0.95f
#define C_INV_ETA_C (1.0f/0.95f)
#define C_INV_ETA_D (1.0f/0.95f)
#define C_LSLOPE    0.15675f         // 6.6*0.95/40
#define C_KSLOPE    0.10263157894736841f   // 1/eta_d - eta_c
#define C_INV_KSLOPE (1.0f/C_KSLOPE)
#define C_INV_ED_KS (1.0f/0.0975f)   // 1/(eta_d*kslope); 0.0975 = 1-0.95^2 exact

// per-column QP bound + decomposition params (one scalar column)
__device__ __forceinline__ void col_params(float tr, float st, float td, float sd,
                                           float& ymn, float& ymx,
                                           float& a, float& b, float& adlo) {
    bool active  = tr > 0.0f;
    bool can_dis = td > 0.0f;

    adlo = can_dis ? -fminf(C_AD_MAG, C_ETA_D * sd) : 0.0f;

    float L = fminf(fmaxf(C_FINAL_SOC - (tr - 1.0f) * C_LSLOPE, 0.0f), C_FINAL_SOC);

    // y_max: reduce AD first
    float s_hi   = st + C_ETA_C * C_AC_MAX;
    float excess = fmaxf(s_hi - C_FINAL_SOC, 0.0f);
    float ad_red = fminf(excess * C_ETA_D, -adlo);
    float rem    = fmaxf(excess - ad_red * C_INV_ETA_D, 0.0f);
    float ac_hi  = fmaxf(C_AC_MAX - rem * C_INV_ETA_C, 0.0f);
    ymx          = ac_hi - ad_red;

    // y_min: minimize AC+AD subject to SOC1 >= L
    float s_lo    = st + adlo * C_INV_ETA_D;
    float deficit = fmaxf(L - s_lo, 0.0f);
    float ad_inc  = fminf(deficit * C_ETA_D, -adlo);
    float rem2    = fmaxf(deficit - ad_inc * C_INV_ETA_D, 0.0f);
    float ac_lo   = fminf(rem2 * C_INV_ETA_C, C_AC_MAX);
    ymn           = fminf(ac_lo + adlo + ad_inc, ymx);

    // decomposition affine constants:
    //   (soc_t + y/eta_d - U)/kslope = a + y*C_INV_ED_KS
    //   (soc_t + y/eta_d - L)/kslope = b + y*C_INV_ED_KS
    a = (st - C_FINAL_SOC) * C_INV_KSLOPE;
    b = (st - L)           * C_INV_KSLOPE;

    // inactive column: force y=0 -> ac=0 exactly (a<=0 so max(0,a)=0; the
    // clamp chain then yields 0). No separate activity multiplier needed.
    if (!active) { ymn = 0.0f; ymx = 0.0f; }
}

__device__ __forceinline__ float sl_elem(float x, float ymn, float ymx,
                                         float a, float b, float adlo) {
    float y  = fminf(fmaxf(x, ymn), ymx);
    float t  = y * C_INV_ED_KS;
    // ac = clamp: max(y, 0, t+a) then min(ACMAX, y-adlo, t+b) then max 0
    float hi = fmaxf(fmaxf(y, 0.0f), t + a);
    float lo = fminf(fminf(C_AC_MAX, y - adlo), t + b);
    return fmaxf(fminf(hi, lo), 0.0f);
}

__device__ __forceinline__ float4 sl_vec(float4 xv, const float4& mn, const float4& mx,
                                         const float4& aa, const float4& bb,
                                         const float4& al) {
    float4 o;
    o.x = sl_elem(xv.x, mn.x, mx.x, aa.x, bb.x, al.x);
    o.y = sl_elem(xv.y, mn.y, mx.y, aa.y, bb.y, al.y);
    o.z = sl_elem(xv.z, mn.z, mx.z, aa.z, bb.z, al.z);
    o.w = sl_elem(xv.w, mn.w, mx.w, aa.w, bb.w, al.w);
    return o;
}

// grid*block threads must be a multiple of NVEC_COLS (128).
__global__ void __launch_bounds__(256) sl_fused(const float4* __restrict__ x,
                                                float4* __restrict__ out,
                                                const float4* __restrict__ t_rem4,
                                                const float4* __restrict__ soc_t4,
                                                const float4* __restrict__ t_dis4,
                                                const float4* __restrict__ soc_dis4,
                                                int n_rows) {
    int tid   = blockIdx.x * blockDim.x + threadIdx.x;
    int p     = tid & (NVEC_COLS - 1);            // fixed column-vector
    int row0  = tid >> 7;                          // starting row
    int rstep = (gridDim.x * blockDim.x) >> 7;    // row stride

    // inline per-column params (L1 loads, computed once per thread)
    float4 tr = t_rem4[p];
    float4 st = soc_t4[p];
    float4 td = t_dis4[p];
    float4 sd = soc_dis4[p];

    float4 mn, mx, aa, bb, al;
    col_params(tr.x, st.x, td.x, sd.x, mn.x, mx.x, aa.x, bb.x, al.x);
    col_params(tr.y, st.y, td.y, sd.y, mn.y, mx.y, aa.y, bb.y, al.y);
    col_params(tr.z, st.z, td.z, sd.z, mn.z, mx.z, aa.z, bb.z, al.z);
    col_params(tr.w, st.w, td.w, sd.w, mn.w, mx.w, aa.w, bb.w, al.w);

    int r = row0;
    int vstep = rstep * NVEC_COLS;
    // 8-row unrolled main loop: eight independent LDG.128 in flight per thread
    for (; r + 7 * rstep < n_rows; r += 8 * rstep) {
        int v0 = r * NVEC_COLS + p;
        int v1 = v0 + vstep;
        int v2 = v1 + vstep;
        int v3 = v2 + vstep;
        int v4 = v3 + vstep;
        int v5 = v4 + vstep;
        int v6 = v5 + vstep;
        int v7 = v6 + vstep;
        float4 x0 = x[v0];
        float4 x1 = x[v1];
        float4 x2 = x[v2];
        float4 x3 = x[v3];
        float4 x4 = x[v4];
        float4 x5 = x[v5];
        float4 x6 = x[v6];
        float4 x7 = x[v7];
        float4 o0 = sl_vec(x0, mn, mx, aa, bb, al);
        float4 o1 = sl_vec(x1, mn, mx, aa, bb, al);
        float4 o2 = sl_vec(x2, mn, mx, aa, bb, al);
        float4 o3 = sl_vec(x3, mn, mx, aa, bb, al);
        float4 o4 = sl_vec(x4, mn, mx, aa, bb, al);
        float4 o5 = sl_vec(x5, mn, mx, aa, bb, al);
        float4 o6 = sl_vec(x6, mn, mx, aa, bb, al);
        float4 o7 = sl_vec(x7, mn, mx, aa, bb, al);
        __stcs(&out[v0], o0);
        __stcs(&out[v1], o1);
        __stcs(&out[v2], o2);
        __stcs(&out[v3], o3);
        __stcs(&out[v4], o4);
        __stcs(&out[v5], o5);
        __stcs(&out[v6], o6);
        __stcs(&out[v7], o7);
    }
    for (; r < n_rows; r += rstep) {
        int v = r * NVEC_COLS + p;
        __stcs(&out[v], sl_vec(x[v], mn, mx, aa, bb, al));
    }
}

extern "C" void kernel_launch(void* const* d_in, const int* in_sizes, int n_in,
                              void* d_out, int out_size) {
    const float* x       = (const float*)d_in[0];
    const float* t_rem   = (const float*)d_in[1];
    const float* soc_t   = (const float*)d_in[2];
    const float* t_dis   = (const float*)d_in[3];
    const float* soc_dis = (const float*)d_in[4];
    float* out = (float*)d_out;

    int n_rows = in_sizes[0] / D_COLS;   // 32768 for the canonical shape

    // 592 blocks = 148 SMs x 4 blocks: one exact wave at the ~64-reg budget
    // the 8x unroll needs (65536/(64*256) = 4 blocks/SM). 592*256 threads =
    // 1184 row-threads x 128 cols -> ~27.7 rows/thread, 8x unrolled.
    sl_fused<<<592, 256>>>((const float4*)x, (float4*)out,
                           (const float4*)t_rem, (const float4*)soc_t,
                           (const float4*)t_dis, (const float4*)soc_dis,
                           n_rows);
}

// round 14
// speedup vs baseline: 1.3516x; 1.3516x over previous
#include <cuda_runtime.h>
#include <cuda_bf16.h>

// ---------------------------------------------------------------------------
// SafetyLayer: per-car separable QP projection — single fused kernel.
//   FINAL CONFIG (measured best: 22.6us total, 19.9us body, 48 regs).
//   Each thread owns ONE float4 column-vector (4 adjacent columns of D=512),
//   computes its per-column QP bounds inline, then streams down rows with a
//   4x-unrolled load/clip/decompose/store loop. Streaming stores (.cs) keep
//   L2 for the x read stream. Grid = 148 SMs x 5 blocks = 740 = exactly one
//   wave at the 48-reg occupancy limit.
//   DO NOT perturb the loop body codegen: any variant that lands at 40 regs
//   (launch-bounds cap R7, pointer-walk R10, 8x unroll R13) de-batches the
//   four LDG.128 and regresses ~20-35%.
// ---------------------------------------------------------------------------

#define D_COLS      512
#define NVEC_COLS   (D_COLS / 4)     // 128 float4 columns per row

// config constants
#define C_FINAL_SOC 0.97f
#define C_AC_MAX    0.165f           // 6.6/40
#define C_AD_MAG    0.165f
#define C_ETA_C     0.95f
#define C_ETA_D     0.95f
#define C_INV_ETA_C (1.0f/0.95f)
#define C_INV_ETA_D (1.0f/0.95f)
#define C_LSLOPE    0.15675f         // 6.6*0.95/40
#define C_KSLOPE    0.10263157894736841f   // 1/eta_d - eta_c
#define C_INV_KSLOPE (1.0f/C_KSLOPE)
#define C_INV_ED_KS (1.0f/0.0975f)   // 1/(eta_d*kslope); 0.0975 = 1-0.95^2 exact

// per-column QP bound + decomposition params (one scalar column)
__device__ __forceinline__ void col_params(float tr, float st, float td, float sd,
                                           float& ymn, float& ymx,
                                           float& a, float& b, float& adlo) {
    bool active  = tr > 0.0f;
    bool can_dis = td > 0.0f;

    adlo = can_dis ? -fminf(C_AD_MAG, C_ETA_D * sd) : 0.0f;

    float L = fminf(fmaxf(C_FINAL_SOC - (tr - 1.0f) * C_LSLOPE, 0.0f), C_FINAL_SOC);

    // y_max: reduce AD first
    float s_hi   = st + C_ETA_C * C_AC_MAX;
    float excess = fmaxf(s_hi - C_FINAL_SOC, 0.0f);
    float ad_red = fminf(excess * C_ETA_D, -adlo);
    float rem    = fmaxf(excess - ad_red * C_INV_ETA_D, 0.0f);
    float ac_hi  = fmaxf(C_AC_MAX - rem * C_INV_ETA_C, 0.0f);
    ymx          = ac_hi - ad_red;

    // y_min: minimize AC+AD subject to SOC1 >= L
    float s_lo    = st + adlo * C_INV_ETA_D;
    float deficit = fmaxf(L - s_lo, 0.0f);
    float ad_inc  = fminf(deficit * C_ETA_D, -adlo);
    float rem2    = fmaxf(deficit - ad_inc * C_INV_ETA_D, 0.0f);
    float ac_lo   = fminf(rem2 * C_INV_ETA_C, C_AC_MAX);
    ymn           = fminf(ac_lo + adlo + ad_inc, ymx);

    // decomposition affine constants:
    //   (soc_t + y/eta_d - U)/kslope = a + y*C_INV_ED_KS
    //   (soc_t + y/eta_d - L)/kslope = b + y*C_INV_ED_KS
    a = (st - C_FINAL_SOC) * C_INV_KSLOPE;
    b = (st - L)           * C_INV_KSLOPE;

    // inactive column: force y=0 -> ac=0 exactly (a<=0 so max(0,a)=0; the
    // clamp chain then yields 0). No separate activity multiplier needed.
    if (!active) { ymn = 0.0f; ymx = 0.0f; }
}

__device__ __forceinline__ float sl_elem(float x, float ymn, float ymx,
                                         float a, float b, float adlo) {
    float y  = fminf(fmaxf(x, ymn), ymx);
    float t  = y * C_INV_ED_KS;
    // ac = clamp: max(y, 0, t+a) then min(ACMAX, y-adlo, t+b) then max 0
    float hi = fmaxf(fmaxf(y, 0.0f), t + a);
    float lo = fminf(fminf(C_AC_MAX, y - adlo), t + b);
    return fmaxf(fminf(hi, lo), 0.0f);
}

__device__ __forceinline__ float4 sl_vec(float4 xv, const float4& mn, const float4& mx,
                                         const float4& aa, const float4& bb,
                                         const float4& al) {
    float4 o;
    o.x = sl_elem(xv.x, mn.x, mx.x, aa.x, bb.x, al.x);
    o.y = sl_elem(xv.y, mn.y, mx.y, aa.y, bb.y, al.y);
    o.z = sl_elem(xv.z, mn.z, mx.z, aa.z, bb.z, al.z);
    o.w = sl_elem(xv.w, mn.w, mx.w, aa.w, bb.w, al.w);
    return o;
}

// grid*block threads must be a multiple of NVEC_COLS (128).
__global__ void __launch_bounds__(256) sl_fused(const float4* __restrict__ x,
                                                float4* __restrict__ out,
                                                const float4* __restrict__ t_rem4,
                                                const float4* __restrict__ soc_t4,
                                                const float4* __restrict__ t_dis4,
                                                const float4* __restrict__ soc_dis4,
                                                int n_rows) {
    int tid   = blockIdx.x * blockDim.x + threadIdx.x;
    int p     = tid & (NVEC_COLS - 1);            // fixed column-vector
    int row0  = tid >> 7;                          // starting row
    int rstep = (gridDim.x * blockDim.x) >> 7;    // row stride

    // inline per-column params (L1 loads, computed once per thread)
    float4 tr = t_rem4[p];
    float4 st = soc_t4[p];
    float4 td = t_dis4[p];
    float4 sd = soc_dis4[p];

    float4 mn, mx, aa, bb, al;
    col_params(tr.x, st.x, td.x, sd.x, mn.x, mx.x, aa.x, bb.x, al.x);
    col_params(tr.y, st.y, td.y, sd.y, mn.y, mx.y, aa.y, bb.y, al.y);
    col_params(tr.z, st.z, td.z, sd.z, mn.z, mx.z, aa.z, bb.z, al.z);
    col_params(tr.w, st.w, td.w, sd.w, mn.w, mx.w, aa.w, bb.w, al.w);

    int r = row0;
    int vstep = rstep * NVEC_COLS;
    // 4-row unrolled main loop: four independent LDG.128 in flight per thread
    for (; r + 3 * rstep < n_rows; r += 4 * rstep) {
        int v0 = r * NVEC_COLS + p;
        int v1 = v0 + vstep;
        int v2 = v1 + vstep;
        int v3 = v2 + vstep;
        float4 x0 = x[v0];
        float4 x1 = x[v1];
        float4 x2 = x[v2];
        float4 x3 = x[v3];
        float4 o0 = sl_vec(x0, mn, mx, aa, bb, al);
        float4 o1 = sl_vec(x1, mn, mx, aa, bb, al);
        float4 o2 = sl_vec(x2, mn, mx, aa, bb, al);
        float4 o3 = sl_vec(x3, mn, mx, aa, bb, al);
        __stcs(&out[v0], o0);
        __stcs(&out[v1], o1);
        __stcs(&out[v2], o2);
        __stcs(&out[v3], o3);
    }
    for (; r < n_rows; r += rstep) {
        int v = r * NVEC_COLS + p;
        __stcs(&out[v], sl_vec(x[v], mn, mx, aa, bb, al));
    }
}

extern "C" void kernel_launch(void* const* d_in, const int* in_sizes, int n_in,
                              void* d_out, int out_size) {
    const float* x       = (const float*)d_in[0];
    const float* t_rem   = (const float*)d_in[1];
    const float* soc_t   = (const float*)d_in[2];
    const float* t_dis   = (const float*)d_in[3];
    const float* soc_dis = (const float*)d_in[4];
    float* out = (float*)d_out;

    int n_rows = in_sizes[0] / D_COLS;   // 32768 for the canonical shape

    // 740 blocks = 148 SMs x 5 blocks: exactly ONE full wave at the 48-reg
    // occupancy limit (5 blocks/SM). 740*256 = 189440 threads = 1480
    // row-threads x 128 cols -> ~22 row-iterations per thread, 4x unrolled.
    sl_fused<<<740, 256>>>((const float4*)x, (float4*)out,
                           (const float4*)t_rem, (const float4*)soc_t,
                           (const float4*)t_dis, (const float4*)soc_dis,
                           n_rows);
}

// round 16
// speedup vs baseline: 1.3631x; 1.0085x over previous
#include <cuda_runtime.h>
#include <cuda_bf16.h>

// ---------------------------------------------------------------------------
// SafetyLayer: per-car separable QP projection — single fused kernel.
//   FINAL CONFIG (measured best, reproduced twice: 22.6/22.75us total,
//   19.9/20.0us body, 48 regs).
//   Each thread owns ONE float4 column-vector (4 adjacent columns of D=512),
//   computes its per-column QP bounds inline, then streams down rows with a
//   4x-unrolled load/clip/decompose/store loop. Streaming stores (.cs) keep
//   L2 for the x read stream. Grid = 148 SMs x 5 blocks = 740 = exactly one
//   wave at the 48-reg occupancy limit.
//   DO NOT perturb the loop body codegen: any variant that lands at 40 regs
//   (launch-bounds cap R7, pointer-walk R10, 8x unroll R13) de-batches the
//   four LDG.128 and regresses 20-35%. Packed f32x2 min/max does not exist
//   in PTX (R14 compile fail) — only add/mul/fma have f32x2 forms.
// ---------------------------------------------------------------------------

#define D_COLS      512
#define NVEC_COLS   (D_COLS / 4)     // 128 float4 columns per row

// config constants
#define C_FINAL_SOC 0.97f
#define C_AC_MAX    0.165f           // 6.6/40
#define C_AD_MAG    0.165f
#define C_ETA_C     0.95f
#define C_ETA_D     0.95f
#define C_INV_ETA_C (1.0f/0.95f)
#define C_INV_ETA_D (1.0f/0.95f)
#define C_LSLOPE    0.15675f         // 6.6*0.95/40
#define C_KSLOPE    0.10263157894736841f   // 1/eta_d - eta_c
#define C_INV_KSLOPE (1.0f/C_KSLOPE)
#define C_INV_ED_KS (1.0f/0.0975f)   // 1/(eta_d*kslope); 0.0975 = 1-0.95^2 exact

// per-column QP bound + decomposition params (one scalar column)
__device__ __forceinline__ void col_params(float tr, float st, float td, float sd,
                                           float& ymn, float& ymx,
                                           float& a, float& b, float& adlo) {
    bool active  = tr > 0.0f;
    bool can_dis = td > 0.0f;

    adlo = can_dis ? -fminf(C_AD_MAG, C_ETA_D * sd) : 0.0f;

    float L = fminf(fmaxf(C_FINAL_SOC - (tr - 1.0f) * C_LSLOPE, 0.0f), C_FINAL_SOC);

    // y_max: reduce AD first
    float s_hi   = st + C_ETA_C * C_AC_MAX;
    float excess = fmaxf(s_hi - C_FINAL_SOC, 0.0f);
    float ad_red = fminf(excess * C_ETA_D, -adlo);
    float rem    = fmaxf(excess - ad_red * C_INV_ETA_D, 0.0f);
    float ac_hi  = fmaxf(C_AC_MAX - rem * C_INV_ETA_C, 0.0f);
    ymx          = ac_hi - ad_red;

    // y_min: minimize AC+AD subject to SOC1 >= L
    float s_lo    = st + adlo * C_INV_ETA_D;
    float deficit = fmaxf(L - s_lo, 0.0f);
    float ad_inc  = fminf(deficit * C_ETA_D, -adlo);
    float rem2    = fmaxf(deficit - ad_inc * C_INV_ETA_D, 0.0f);
    float ac_lo   = fminf(rem2 * C_INV_ETA_C, C_AC_MAX);
    ymn           = fminf(ac_lo + adlo + ad_inc, ymx);

    // decomposition affine constants:
    //   (soc_t + y/eta_d - U)/kslope = a + y*C_INV_ED_KS
    //   (soc_t + y/eta_d - L)/kslope = b + y*C_INV_ED_KS
    a = (st - C_FINAL_SOC) * C_INV_KSLOPE;
    b = (st - L)           * C_INV_KSLOPE;

    // inactive column: force y=0 -> ac=0 exactly (a<=0 so max(0,a)=0; the
    // clamp chain then yields 0). No separate activity multiplier needed.
    if (!active) { ymn = 0.0f; ymx = 0.0f; }
}

__device__ __forceinline__ float sl_elem(float x, float ymn, float ymx,
                                         float a, float b, float adlo) {
    float y  = fminf(fmaxf(x, ymn), ymx);
    float t  = y * C_INV_ED_KS;
    // ac = clamp: max(y, 0, t+a) then min(ACMAX, y-adlo, t+b) then max 0
    float hi = fmaxf(fmaxf(y, 0.0f), t + a);
    float lo = fminf(fminf(C_AC_MAX, y - adlo), t + b);
    return fmaxf(fminf(hi, lo), 0.0f);
}

__device__ __forceinline__ float4 sl_vec(float4 xv, const float4& mn, const float4& mx,
                                         const float4& aa, const float4& bb,
                                         const float4& al) {
    float4 o;
    o.x = sl_elem(xv.x, mn.x, mx.x, aa.x, bb.x, al.x);
    o.y = sl_elem(xv.y, mn.y, mx.y, aa.y, bb.y, al.y);
    o.z = sl_elem(xv.z, mn.z, mx.z, aa.z, bb.z, al.z);
    o.w = sl_elem(xv.w, mn.w, mx.w, aa.w, bb.w, al.w);
    return o;
}

// grid*block threads must be a multiple of NVEC_COLS (128).
__global__ void __launch_bounds__(256) sl_fused(const float4* __restrict__ x,
                                                float4* __restrict__ out,
                                                const float4* __restrict__ t_rem4,
                                                const float4* __restrict__ soc_t4,
                                                const float4* __restrict__ t_dis4,
                                                const float4* __restrict__ soc_dis4,
                                                int n_rows) {
    int tid   = blockIdx.x * blockDim.x + threadIdx.x;
    int p     = tid & (NVEC_COLS - 1);            // fixed column-vector
    int row0  = tid >> 7;                          // starting row
    int rstep = (gridDim.x * blockDim.x) >> 7;    // row stride

    // inline per-column params (L1 loads, computed once per thread)
    float4 tr = t_rem4[p];
    float4 st = soc_t4[p];
    float4 td = t_dis4[p];
    float4 sd = soc_dis4[p];

    float4 mn, mx, aa, bb, al;
    col_params(tr.x, st.x, td.x, sd.x, mn.x, mx.x, aa.x, bb.x, al.x);
    col_params(tr.y, st.y, td.y, sd.y, mn.y, mx.y, aa.y, bb.y, al.y);
    col_params(tr.z, st.z, td.z, sd.z, mn.z, mx.z, aa.z, bb.z, al.z);
    col_params(tr.w, st.w, td.w, sd.w, mn.w, mx.w, aa.w, bb.w, al.w);

    int r = row0;
    int vstep = rstep * NVEC_COLS;
    // 4-row unrolled main loop: four independent LDG.128 in flight per thread
    for (; r + 3 * rstep < n_rows; r += 4 * rstep) {
        int v0 = r * NVEC_COLS + p;
        int v1 = v0 + vstep;
        int v2 = v1 + vstep;
        int v3 = v2 + vstep;
        float4 x0 = x[v0];
        float4 x1 = x[v1];
        float4 x2 = x[v2];
        float4 x3 = x[v3];
        float4 o0 = sl_vec(x0, mn, mx, aa, bb, al);
        float4 o1 = sl_vec(x1, mn, mx, aa, bb, al);
        float4 o2 = sl_vec(x2, mn, mx, aa, bb, al);
        float4 o3 = sl_vec(x3, mn, mx, aa, bb, al);
        __stcs(&out[v0], o0);
        __stcs(&out[v1], o1);
        __stcs(&out[v2], o2);
        __stcs(&out[v3], o3);
    }
    for (; r < n_rows; r += rstep) {
        int v = r * NVEC_COLS + p;
        __stcs(&out[v], sl_vec(x[v], mn, mx, aa, bb, al));
    }
}

extern "C" void kernel_launch(void* const* d_in, const int* in_sizes, int n_in,
                              void* d_out, int out_size) {
    const float* x       = (const float*)d_in[0];
    const float* t_rem   = (const float*)d_in[1];
    const float* soc_t   = (const float*)d_in[2];
    const float* t_dis   = (const float*)d_in[3];
    const float* soc_dis = (const float*)d_in[4];
    float* out = (float*)d_out;

    int n_rows = in_sizes[0] / D_COLS;   // 32768 for the canonical shape

    // 740 blocks = 148 SMs x 5 blocks: exactly ONE full wave at the 48-reg
    // occupancy limit (5 blocks/SM). 740*256 = 189440 threads = 1480
    // row-threads x 128 cols -> ~22 row-iterations per thread, 4x unrolled.
    sl_fused<<<740, 256>>>((const float4*)x, (float4*)out,
                           (const float4*)t_rem, (const float4*)soc_t,
                           (const float4*)t_dis, (const float4*)soc_dis,
                           n_rows);
}